// round 7
// baseline (speedup 1.0000x reference)
#include <cuda_runtime.h>
#include <cuda_bf16.h>
#include <math.h>
#include <stdint.h>

// Problem constants
constexpr int B   = 2;
constexpr int S   = 2048;
constexpr int E   = 1024;
constexpr int H   = 16;
constexpr int DH  = 64;
constexpr int MLP = 4096;
constexpr int M   = B * S;       // 4096 rows
constexpr float SCALE = 0.125f;  // 1/sqrt(64)
constexpr int NBR  = S / 8;      // 256 block-rows (VEC = 8)
constexpr int CAP  = 512;        // max active cols per block-row

// ---------------------------------------------------------------------------
// Scratch buffers (device globals)
// ---------------------------------------------------------------------------
__device__ __nv_bfloat16 g_a1h[M * E],     g_a1l[M * E];      // LN1 out (split)
__device__ __nv_bfloat16 g_w1h[3 * E * E], g_w1l[3 * E * E];  // w_qkv
__device__ __nv_bfloat16 g_w2h[E * E],     g_w2l[E * E];      // w_out
__device__ __nv_bfloat16 g_w3h[MLP * E],   g_w3l[MLP * E];    // w1
__device__ __nv_bfloat16 g_w4h[E * MLP],   g_w4l[E * MLP];    // w2
__device__ float         g_qkv[M * 3 * E];                    // QKV (fp32 for attn)
__device__ __nv_bfloat16 g_cxh[M * E],     g_cxl[M * E];      // ctx (split)
__device__ float         g_att[M * E];                        // outproj + residual
__device__ __nv_bfloat16 g_a2h[M * E],     g_a2l[M * E];      // LN2 out (split)
__device__ __nv_bfloat16 g_m1h[M * MLP],   g_m1l[M * MLP];    // MLP hidden (split)
__device__ unsigned char g_mask[S * S];
__device__ int g_mask_sz;
__device__ int           g_idx [NBR * CAP];
__device__ unsigned char g_bits[NBR * CAP];
__device__ int           g_nact[NBR];

// ---------------------------------------------------------------------------
// PTX helpers
// ---------------------------------------------------------------------------
__device__ __forceinline__ uint32_t smem_u32(const void* p) {
    uint32_t a;
    asm("{ .reg .u64 t; cvta.to.shared.u64 t, %1; cvt.u32.u64 %0, t; }"
        : "=r"(a) : "l"(p));
    return a;
}
__device__ __forceinline__ void cp_async16(uint32_t saddr, const void* gptr) {
    asm volatile("cp.async.cg.shared.global [%0], [%1], 16;"
                 :: "r"(saddr), "l"(__cvta_generic_to_global(gptr)) : "memory");
}
#define CP_COMMIT() asm volatile("cp.async.commit_group;" ::: "memory")
#define CP_WAIT(n)  asm volatile("cp.async.wait_group %0;" :: "n"(n) : "memory")

__device__ __forceinline__ uint4 ldmx4(uint32_t a) {
    uint4 r;
    asm volatile("ldmatrix.sync.aligned.m8n8.x4.shared.b16 {%0,%1,%2,%3}, [%4];"
                 : "=r"(r.x), "=r"(r.y), "=r"(r.z), "=r"(r.w) : "r"(a));
    return r;
}
__device__ __forceinline__ void mma_bf16(float* d, const uint4& a, uint32_t b0, uint32_t b1)
{
    asm volatile(
        "mma.sync.aligned.m16n8k16.row.col.f32.bf16.bf16.f32 "
        "{%0,%1,%2,%3}, {%4,%5,%6,%7}, {%8,%9}, {%0,%1,%2,%3};"
        : "+f"(d[0]), "+f"(d[1]), "+f"(d[2]), "+f"(d[3])
        : "r"(a.x), "r"(a.y), "r"(a.z), "r"(a.w), "r"(b0), "r"(b1));
}
__device__ __forceinline__ void split2(float f0, float f1, uint32_t& hi, uint32_t& lo)
{
    __nv_bfloat162 h = __float22bfloat162_rn(make_float2(f0, f1));
    float2 hf = __bfloat1622float2(h);
    __nv_bfloat162 l = __float22bfloat162_rn(make_float2(f0 - hf.x, f1 - hf.y));
    hi = *reinterpret_cast<uint32_t*>(&h);
    lo = *reinterpret_cast<uint32_t*>(&l);
}

// ---------------------------------------------------------------------------
// Mask dtype detection + canonicalization (known-good)
// ---------------------------------------------------------------------------
__global__ void mask_detect_kernel(const unsigned char* __restrict__ m)
{
    if (threadIdx.x == 0 && blockIdx.x == 0) {
        bool is1 = false, is2 = false;
        for (int p = 0; p < 8192; p++) {
            unsigned char v = m[p];
            if (v == 1u    && (p & 3) != 0) is1 = true;
            if (v == 0x3Fu && (p & 3) == 1) is2 = true;
        }
        g_mask_sz = is1 ? 1 : (is2 ? 2 : 4);
    }
}

__global__ __launch_bounds__(256) void mask_convert_kernel(
    const unsigned char* __restrict__ m, unsigned char* __restrict__ out)
{
    const int idx = blockIdx.x * 256 + threadIdx.x;
    const int sz = g_mask_sz;
    unsigned char nz = 0;
    const unsigned char* p = m + (size_t)idx * sz;
    for (int i = 0; i < sz; i++) nz |= p[i];
    out[idx] = nz ? 1 : 0;
}

// ---------------------------------------------------------------------------
// Build per-block-row active-column lists (known-good)
// ---------------------------------------------------------------------------
__global__ __launch_bounds__(256) void build_idx_kernel(
    const unsigned char* __restrict__ mask,
    int* __restrict__ idx, unsigned char* __restrict__ bits, int* __restrict__ nact)
{
    __shared__ unsigned char tb[S];
    __shared__ int cnt[256];

    const int t  = threadIdx.x;
    const int br = blockIdx.x;

    int local = 0;
#pragma unroll
    for (int j = 0; j < 8; j++) {
        int c = t * 8 + j;
        unsigned char bt = 0;
#pragma unroll
        for (int r = 0; r < 8; r++)
            bt |= (mask[(size_t)(br * 8 + r) * S + c] ? 1u : 0u) << r;
        tb[c] = bt;
        local += (bt != 0);
    }
    cnt[t] = local;
    __syncthreads();

    if (t == 0) {
        int run = 0;
        for (int i = 0; i < 256; i++) { int v = cnt[i]; cnt[i] = run; run += v; }
        nact[br] = run < CAP ? run : CAP;
    }
    __syncthreads();

    int pos = cnt[t];
#pragma unroll
    for (int j = 0; j < 8; j++) {
        int c = t * 8 + j;
        if (tb[c] && pos < CAP) {
            idx [br * CAP + pos] = c;
            bits[br * CAP + pos] = tb[c];
            pos++;
        }
    }
}

// ---------------------------------------------------------------------------
// Weight split: fp32 -> bf16 hi/lo. One float4 per thread.
// ---------------------------------------------------------------------------
__global__ __launch_bounds__(256) void conv_split_kernel(
    const float* __restrict__ in,
    __nv_bfloat16* __restrict__ hi, __nv_bfloat16* __restrict__ lo)
{
    const int i = blockIdx.x * 256 + threadIdx.x;   // float4 index
    float4 v = reinterpret_cast<const float4*>(in)[i];
    uint32_t h0, l0, h1, l1;
    split2(v.x, v.y, h0, l0);
    split2(v.z, v.w, h1, l1);
    reinterpret_cast<uint2*>(hi)[i] = make_uint2(h0, h1);
    reinterpret_cast<uint2*>(lo)[i] = make_uint2(l0, l1);
}

// ---------------------------------------------------------------------------
// LayerNorm emitting bf16 hi/lo split
// ---------------------------------------------------------------------------
__global__ __launch_bounds__(256) void ln_split_kernel(
    const float* __restrict__ in, const float* __restrict__ g,
    const float* __restrict__ beta,
    __nv_bfloat16* __restrict__ oh, __nv_bfloat16* __restrict__ ol)
{
    __shared__ float sred[256];
    const int tid = threadIdx.x;
    const size_t row = blockIdx.x;
    const float* x = in + row * E;

    float v[4];
    float s = 0.f;
#pragma unroll
    for (int i = 0; i < 4; i++) { v[i] = x[tid + i * 256]; s += v[i]; }

    sred[tid] = s; __syncthreads();
#pragma unroll
    for (int off = 128; off > 0; off >>= 1) {
        if (tid < off) sred[tid] += sred[tid + off];
        __syncthreads();
    }
    const float mu = sred[0] * (1.f / E);
    __syncthreads();

    float sq = 0.f;
#pragma unroll
    for (int i = 0; i < 4; i++) { float d = v[i] - mu; sq += d * d; }
    sred[tid] = sq; __syncthreads();
#pragma unroll
    for (int off = 128; off > 0; off >>= 1) {
        if (tid < off) sred[tid] += sred[tid + off];
        __syncthreads();
    }
    const float rstd = rsqrtf(sred[0] * (1.f / E) + 1e-5f);

#pragma unroll
    for (int i = 0; i < 4; i++) {
        int c = tid + i * 256;
        float y = (v[i] - mu) * rstd * g[c] + beta[c];
        __nv_bfloat16 hb = __float2bfloat16(y);
        oh[row * E + c] = hb;
        ol[row * E + c] = __float2bfloat16(y - __bfloat162float(hb));
    }
}

// ---------------------------------------------------------------------------
// bf16 split-3 GEMM, cp.async + ldmatrix, 2 CTAs/SM.
// Block 128x128x32, 256 threads (8 warps, 4m x 2n), warp tile 32x64, 3 stages.
// Stage (32KB): [Ah 8K][Al 8K][Bh 8K][Bl 8K]; rows 64B, 16B-chunk XOR swizzle.
// EPI: 0 = fp32, 1 = fp32 + residual, 2 = bf16 hi/lo split
// ---------------------------------------------------------------------------
constexpr int STAGES = 3;
constexpr int STAGE_BYTES = 32768;
constexpr int GEMM_SMEM = STAGES * STAGE_BYTES;   // 96KB

template <int EPI>
__global__ __launch_bounds__(256, 2) void gemm3(
    const __nv_bfloat16* __restrict__ Ah, const __nv_bfloat16* __restrict__ Al,
    const __nv_bfloat16* __restrict__ Bh, const __nv_bfloat16* __restrict__ Bl,
    const float* __restrict__ bias, const float* __restrict__ R,
    float* __restrict__ C, __nv_bfloat16* __restrict__ Ch, __nv_bfloat16* __restrict__ Cl,
    int Nn, int Kk)
{
    extern __shared__ char smem[];
    const uint32_t sb = smem_u32(smem);

    const int tid  = threadIdx.x;
    const int lane = tid & 31;
    const int wid  = tid >> 5;
    const int wm   = wid >> 1;   // 0..3
    const int wn   = wid & 1;    // 0..1
    const int m0 = blockIdx.y * 128;
    const int n0 = blockIdx.x * 128;

    // ---- loader: thread owns 2 adjacent 16B chunks of each of 4 tiles ----
    const int lr  = tid >> 1;          // row 0..127
    const int lcb = (tid & 1) * 2;     // chunks lcb, lcb+1
    const uint32_t sp0 = (uint32_t)(lr * 4 + ((lcb + 0) ^ ((lr >> 1) & 3))) * 16;
    const uint32_t sp1 = (uint32_t)(lr * 4 + ((lcb + 1) ^ ((lr >> 1) & 3))) * 16;
    const __nv_bfloat16* gAh = Ah + (size_t)(m0 + lr) * Kk + lcb * 8;
    const __nv_bfloat16* gAl = Al + (size_t)(m0 + lr) * Kk + lcb * 8;
    const __nv_bfloat16* gBh = Bh + (size_t)(n0 + lr) * Kk + lcb * 8;
    const __nv_bfloat16* gBl = Bl + (size_t)(n0 + lr) * Kk + lcb * 8;

    auto load_stage = [&](int stage, int kt) {
        const uint32_t s0 = sb + stage * STAGE_BYTES;
        const int go = kt * 32;
        cp_async16(s0 + sp0,         gAh + go);
        cp_async16(s0 + sp1,         gAh + go + 8);
        cp_async16(s0 + sp0 + 8192,  gAl + go);
        cp_async16(s0 + sp1 + 8192,  gAl + go + 8);
        cp_async16(s0 + sp0 + 16384, gBh + go);
        cp_async16(s0 + sp1 + 16384, gBh + go + 8);
        cp_async16(s0 + sp0 + 24576, gBl + go);
        cp_async16(s0 + sp1 + 24576, gBl + go + 8);
    };

    // ---- fragment address components ----
    const int arow0 = wm * 32 + (lane & 15);
    const int achb  = lane >> 4;
    const int brow0 = wn * 64 + (lane & 7) + ((lane >> 4) << 3);
    const int bchb  = (lane >> 3) & 1;

    float acc[2][8][4];
#pragma unroll
    for (int mi = 0; mi < 2; mi++)
#pragma unroll
        for (int ni = 0; ni < 8; ni++)
#pragma unroll
            for (int q = 0; q < 4; q++) acc[mi][ni][q] = 0.f;

    const int T = Kk >> 5;

    load_stage(0, 0); CP_COMMIT();
    load_stage(1, 1); CP_COMMIT();

    int stage = 0;
    for (int t = 0; t < T; t++) {
        if (t + 2 < T) load_stage((stage + 2) % STAGES, t + 2);
        CP_COMMIT();
        CP_WAIT(2);
        __syncthreads();

        const uint32_t base = sb + stage * STAGE_BYTES;
#pragma unroll
        for (int ks = 0; ks < 2; ks++) {
            uint4 ah[2], al[2];
#pragma unroll
            for (int mi = 0; mi < 2; mi++) {
                int row = arow0 + mi * 16;
                int c = ks * 2 + achb;
                uint32_t ad = base + (uint32_t)(row * 4 + (c ^ ((row >> 1) & 3))) * 16;
                ah[mi] = ldmx4(ad);
                al[mi] = ldmx4(ad + 8192);
            }
            uint4 bh[4], bl[4];
#pragma unroll
            for (int np = 0; np < 4; np++) {
                int row = brow0 + np * 16;
                int c = ks * 2 + bchb;
                uint32_t bd = base + 16384 + (uint32_t)(row * 4 + (c ^ ((row >> 1) & 3))) * 16;
                bh[np] = ldmx4(bd);
                bl[np] = ldmx4(bd + 8192);
            }
            uint32_t bh0[8], bh1[8], bl0[8], bl1[8];
#pragma unroll
            for (int np = 0; np < 4; np++) {
                bh0[2 * np] = bh[np].x; bh0[2 * np + 1] = bh[np].z;
                bh1[2 * np] = bh[np].y; bh1[2 * np + 1] = bh[np].w;
                bl0[2 * np] = bl[np].x; bl0[2 * np + 1] = bl[np].z;
                bl1[2 * np] = bl[np].y; bl1[2 * np + 1] = bl[np].w;
            }
#pragma unroll
            for (int mi = 0; mi < 2; mi++)
#pragma unroll
                for (int ni = 0; ni < 8; ni++)
                    mma_bf16(acc[mi][ni], ah[mi], bh0[ni], bh1[ni]);
#pragma unroll
            for (int mi = 0; mi < 2; mi++)
#pragma unroll
                for (int ni = 0; ni < 8; ni++)
                    mma_bf16(acc[mi][ni], ah[mi], bl0[ni], bl1[ni]);
#pragma unroll
            for (int mi = 0; mi < 2; mi++)
#pragma unroll
                for (int ni = 0; ni < 8; ni++)
                    mma_bf16(acc[mi][ni], al[mi], bh0[ni], bh1[ni]);
        }
        __syncthreads();
        stage = (stage + 1) % STAGES;
    }

    // ---- epilogue ----
    const int rb = m0 + wm * 32 + (lane >> 2);
    const int cb = n0 + wn * 64 + (lane & 3) * 2;
#pragma unroll
    for (int mi = 0; mi < 2; mi++) {
#pragma unroll
        for (int ni = 0; ni < 8; ni++) {
            const int col = cb + ni * 8;
            const float2 bv = *reinterpret_cast<const float2*>(&bias[col]);
#pragma unroll
            for (int half = 0; half < 2; half++) {
                const size_t row = (size_t)(rb + mi * 16 + half * 8);
                float ox = acc[mi][ni][half * 2 + 0] + bv.x;
                float oy = acc[mi][ni][half * 2 + 1] + bv.y;
                if (EPI == 1) {
                    float2 rv = *reinterpret_cast<const float2*>(&R[row * Nn + col]);
                    ox += rv.x; oy += rv.y;
                }
                if (EPI == 2) {
                    uint32_t hh, ll;
                    split2(ox, oy, hh, ll);
                    *reinterpret_cast<uint32_t*>(&Ch[row * Nn + col]) = hh;
                    *reinterpret_cast<uint32_t*>(&Cl[row * Nn + col]) = ll;
                } else {
                    *reinterpret_cast<float2*>(&C[row * Nn + col]) = make_float2(ox, oy);
                }
            }
        }
    }
}

// ---------------------------------------------------------------------------
// Block-sparse attention (known-good), emits bf16 hi/lo ctx
// ---------------------------------------------------------------------------
__global__ __launch_bounds__(256) void attn_sparse_kernel(
    const float* __restrict__ qkv,
    const int* __restrict__ idx_g, const unsigned char* __restrict__ bits_g,
    const int* __restrict__ nact_g,
    __nv_bfloat16* __restrict__ cxh, __nv_bfloat16* __restrict__ cxl)
{
    __shared__ float Qs[8][64];
    __shared__ float Ss[8][CAP];
    __shared__ int sidx[CAP];
    __shared__ unsigned char sbits[CAP];

    const int tid = threadIdx.x;
    const int br = blockIdx.x;
    const int hd = blockIdx.y;
    const int b  = blockIdx.z;
    const int q0 = br * 8;
    const int n  = nact_g[br];

    for (int i = tid; i < CAP; i += 256) {
        sidx[i]  = idx_g[br * CAP + i];
        sbits[i] = bits_g[br * CAP + i];
    }

    const size_t base = (size_t)b * S * (3 * E);
    const float* Qbase = qkv + base + (size_t)q0 * (3 * E) + hd * DH;
    const float* Kbase = qkv + base + E + hd * DH;
    const float* Vbase = qkv + base + 2 * E + hd * DH;

    {
        int r = tid >> 5;
        int c = (tid & 31) * 2;
        *reinterpret_cast<float2*>(&Qs[r][c]) =
            *reinterpret_cast<const float2*>(Qbase + (size_t)r * (3 * E) + c);
    }
    __syncthreads();

    for (int s = tid; s < n; s += 256) {
        const float4* kr = reinterpret_cast<const float4*>(Kbase + (size_t)sidx[s] * (3 * E));
        float a[8];
#pragma unroll
        for (int r = 0; r < 8; r++) a[r] = 0.f;
#pragma unroll 4
        for (int d4 = 0; d4 < 16; d4++) {
            float4 kv = kr[d4];
#pragma unroll
            for (int r = 0; r < 8; r++) {
                float4 qv = reinterpret_cast<const float4*>(&Qs[r][0])[d4];
                a[r] = fmaf(kv.x, qv.x, a[r]);
                a[r] = fmaf(kv.y, qv.y, a[r]);
                a[r] = fmaf(kv.z, qv.z, a[r]);
                a[r] = fmaf(kv.w, qv.w, a[r]);
            }
        }
        unsigned bt = sbits[s];
#pragma unroll
        for (int r = 0; r < 8; r++)
            Ss[r][s] = ((bt >> r) & 1) ? a[r] * SCALE : -1e9f;
    }
    __syncthreads();

    const int w = tid >> 5, l = tid & 31;
    float mx = -3.0e38f;
    for (int s = l; s < n; s += 32) mx = fmaxf(mx, Ss[w][s]);
#pragma unroll
    for (int o = 16; o; o >>= 1) mx = fmaxf(mx, __shfl_xor_sync(0xFFFFFFFFu, mx, o));
    float sm = 0.f;
    for (int s = l; s < n; s += 32) {
        float p = __expf(Ss[w][s] - mx);
        Ss[w][s] = p;
        sm += p;
    }
#pragma unroll
    for (int o = 16; o; o >>= 1) sm += __shfl_xor_sync(0xFFFFFFFFu, sm, o);
    const float inv = 1.f / sm;
    __syncwarp();

    float ax = 0.f, ay = 0.f;
    int s = 0;
    for (; s + 4 <= n; s += 4) {
#pragma unroll
        for (int u = 0; u < 4; u++) {
            float p = Ss[w][s + u];
            const float2 v = *reinterpret_cast<const float2*>(
                Vbase + (size_t)sidx[s + u] * (3 * E) + 2 * l);
            ax = fmaf(p, v.x, ax);
            ay = fmaf(p, v.y, ay);
        }
    }
    for (; s < n; s++) {
        float p = Ss[w][s];
        const float2 v = *reinterpret_cast<const float2*>(
            Vbase + (size_t)sidx[s] * (3 * E) + 2 * l);
        ax = fmaf(p, v.x, ax);
        ay = fmaf(p, v.y, ay);
    }
    float ox = ax * inv, oy = ay * inv;
    uint32_t hh, ll;
    split2(ox, oy, hh, ll);
    const size_t off = ((size_t)b * S + q0 + w) * E + hd * DH + 2 * l;
    *reinterpret_cast<uint32_t*>(&cxh[off]) = hh;
    *reinterpret_cast<uint32_t*>(&cxl[off]) = ll;
}

// ---------------------------------------------------------------------------
// Launch (ordered so QKV gemm3 is the 4th launch -> gets profiled)
// ---------------------------------------------------------------------------
extern "C" void kernel_launch(void* const* d_in, const int* in_sizes, int n_in,
                              void* d_out, int out_size)
{
    const float*         x      = (const float*)d_in[0];
    const unsigned char* mraw   = (const unsigned char*)d_in[1];
    const float*         w_qkv  = (const float*)d_in[2];
    const float*         b_qkv  = (const float*)d_in[3];
    const float*         w_out  = (const float*)d_in[4];
    const float*         b_out  = (const float*)d_in[5];
    const float*         g1     = (const float*)d_in[6];
    const float*         beta1  = (const float*)d_in[7];
    const float*         g2     = (const float*)d_in[8];
    const float*         beta2  = (const float*)d_in[9];
    const float*         w1     = (const float*)d_in[10];
    const float*         bias1  = (const float*)d_in[11];
    const float*         w2     = (const float*)d_in[12];
    const float*         bias2  = (const float*)d_in[13];
    float*               out    = (float*)d_out;

    __nv_bfloat16 *a1h, *a1l, *w1h, *w1l, *w2h, *w2l, *w3h, *w3l, *w4h, *w4l;
    __nv_bfloat16 *cxh, *cxl, *a2h, *a2l, *m1h, *m1l;
    float *qkv, *att;
    unsigned char *msk, *bits;
    int *idx, *nact;
    cudaGetSymbolAddress((void**)&a1h, g_a1h); cudaGetSymbolAddress((void**)&a1l, g_a1l);
    cudaGetSymbolAddress((void**)&w1h, g_w1h); cudaGetSymbolAddress((void**)&w1l, g_w1l);
    cudaGetSymbolAddress((void**)&w2h, g_w2h); cudaGetSymbolAddress((void**)&w2l, g_w2l);
    cudaGetSymbolAddress((void**)&w3h, g_w3h); cudaGetSymbolAddress((void**)&w3l, g_w3l);
    cudaGetSymbolAddress((void**)&w4h, g_w4h); cudaGetSymbolAddress((void**)&w4l, g_w4l);
    cudaGetSymbolAddress((void**)&cxh, g_cxh); cudaGetSymbolAddress((void**)&cxl, g_cxl);
    cudaGetSymbolAddress((void**)&a2h, g_a2h); cudaGetSymbolAddress((void**)&a2l, g_a2l);
    cudaGetSymbolAddress((void**)&m1h, g_m1h); cudaGetSymbolAddress((void**)&m1l, g_m1l);
    cudaGetSymbolAddress((void**)&qkv, g_qkv);
    cudaGetSymbolAddress((void**)&att, g_att);
    cudaGetSymbolAddress((void**)&msk, g_mask);
    cudaGetSymbolAddress((void**)&idx, g_idx);
    cudaGetSymbolAddress((void**)&bits, g_bits);
    cudaGetSymbolAddress((void**)&nact, g_nact);

    cudaFuncSetAttribute(gemm3<0>, cudaFuncAttributeMaxDynamicSharedMemorySize, GEMM_SMEM);
    cudaFuncSetAttribute(gemm3<1>, cudaFuncAttributeMaxDynamicSharedMemorySize, GEMM_SMEM);
    cudaFuncSetAttribute(gemm3<2>, cudaFuncAttributeMaxDynamicSharedMemorySize, GEMM_SMEM);

    // 1. LN1 -> split
    ln_split_kernel<<<M, 256>>>(x, g1, beta1, a1h, a1l);
    // 2. w_qkv split
    conv_split_kernel<<<3 * E * E / 1024, 256>>>(w_qkv, w1h, w1l);
    // 3. w_out split
    conv_split_kernel<<<E * E / 1024, 256>>>(w_out, w2h, w2l);
    // 4. QKV projection  <-- profiled launch
    gemm3<0><<<dim3(3 * E / 128, M / 128), 256, GEMM_SMEM>>>(
        a1h, a1l, w1h, w1l, b_qkv, nullptr, qkv, nullptr, nullptr, 3 * E, E);
    // 5-7. Mask canonicalization + sparsity index
    mask_detect_kernel<<<1, 32>>>(mraw);
    mask_convert_kernel<<<(S * S) / 256, 256>>>(mraw, msk);
    build_idx_kernel<<<NBR, 256>>>(msk, idx, bits, nact);
    // 8. Block-sparse attention -> ctx split
    attn_sparse_kernel<<<dim3(NBR, H, B), 256>>>(qkv, idx, bits, nact, cxh, cxl);
    // 9. Out projection + residual x
    gemm3<1><<<dim3(E / 128, M / 128), 256, GEMM_SMEM>>>(
        cxh, cxl, w2h, w2l, b_out, x, att, nullptr, nullptr, E, E);
    // 10. LN2 -> split
    ln_split_kernel<<<M, 256>>>(att, g2, beta2, a2h, a2l);
    // 11-12. MLP weight splits
    conv_split_kernel<<<MLP * E / 1024, 256>>>(w1, w3h, w3l);
    conv_split_kernel<<<E * MLP / 1024, 256>>>(w2, w4h, w4l);
    // 13. MLP linear1 (split out)
    gemm3<2><<<dim3(MLP / 128, M / 128), 256, GEMM_SMEM>>>(
        a2h, a2l, w3h, w3l, bias1, nullptr, nullptr, m1h, m1l, MLP, E);
    // 14. MLP linear2 + residual x -> output
    gemm3<1><<<dim3(E / 128, M / 128), 256, GEMM_SMEM>>>(
        m1h, m1l, w4h, w4l, bias2, x, out, nullptr, nullptr, E, MLP);
}

// round 8
// speedup vs baseline: 1.0665x; 1.0665x over previous
#include <cuda_runtime.h>
#include <cuda_bf16.h>
#include <math.h>
#include <stdint.h>

// Problem constants
constexpr int B   = 2;
constexpr int S   = 2048;
constexpr int E   = 1024;
constexpr int H   = 16;
constexpr int DH  = 64;
constexpr int MLP = 4096;
constexpr int M   = B * S;       // 4096 rows
constexpr float SCALE = 0.125f;  // 1/sqrt(64)
constexpr int NBR  = S / 8;      // 256 block-rows (VEC = 8)
constexpr int CAP  = 512;        // max active cols per block-row

// ---------------------------------------------------------------------------
// Scratch buffers (device globals)
// ---------------------------------------------------------------------------
__device__ __nv_bfloat16 g_a1h[M * E],     g_a1l[M * E];      // LN1 out (split)
__device__ __nv_bfloat16 g_w1h[3 * E * E], g_w1l[3 * E * E];  // w_qkv
__device__ __nv_bfloat16 g_w2h[E * E],     g_w2l[E * E];      // w_out
__device__ __nv_bfloat16 g_w3h[MLP * E],   g_w3l[MLP * E];    // w1
__device__ __nv_bfloat16 g_w4h[E * MLP],   g_w4l[E * MLP];    // w2
__device__ float         g_qkv[M * 3 * E];                    // QKV (fp32 for attn)
__device__ __nv_bfloat16 g_cxh[M * E],     g_cxl[M * E];      // ctx (split)
__device__ float         g_att[M * E];                        // outproj + residual
__device__ __nv_bfloat16 g_a2h[M * E],     g_a2l[M * E];      // LN2 out (split)
__device__ __nv_bfloat16 g_m1h[M * MLP],   g_m1l[M * MLP];    // MLP hidden (split)
__device__ int           g_idx [NBR * CAP];
__device__ unsigned char g_bits[NBR * CAP];
__device__ int           g_nact[NBR];

// ---------------------------------------------------------------------------
// PTX helpers
// ---------------------------------------------------------------------------
__device__ __forceinline__ uint32_t smem_u32(const void* p) {
    uint32_t a;
    asm("{ .reg .u64 t; cvta.to.shared.u64 t, %1; cvt.u32.u64 %0, t; }"
        : "=r"(a) : "l"(p));
    return a;
}
__device__ __forceinline__ void cp_async16(uint32_t saddr, const void* gptr) {
    asm volatile("cp.async.cg.shared.global [%0], [%1], 16;"
                 :: "r"(saddr), "l"(__cvta_generic_to_global(gptr)) : "memory");
}
#define CP_COMMIT() asm volatile("cp.async.commit_group;" ::: "memory")
#define CP_WAIT(n)  asm volatile("cp.async.wait_group %0;" :: "n"(n) : "memory")

__device__ __forceinline__ uint4 ldmx4(uint32_t a) {
    uint4 r;
    asm volatile("ldmatrix.sync.aligned.m8n8.x4.shared.b16 {%0,%1,%2,%3}, [%4];"
                 : "=r"(r.x), "=r"(r.y), "=r"(r.z), "=r"(r.w) : "r"(a));
    return r;
}
__device__ __forceinline__ void mma_bf16(float* d, const uint4& a, uint32_t b0, uint32_t b1)
{
    asm volatile(
        "mma.sync.aligned.m16n8k16.row.col.f32.bf16.bf16.f32 "
        "{%0,%1,%2,%3}, {%4,%5,%6,%7}, {%8,%9}, {%0,%1,%2,%3};"
        : "+f"(d[0]), "+f"(d[1]), "+f"(d[2]), "+f"(d[3])
        : "r"(a.x), "r"(a.y), "r"(a.z), "r"(a.w), "r"(b0), "r"(b1));
}
__device__ __forceinline__ void split2(float f0, float f1, uint32_t& hi, uint32_t& lo)
{
    __nv_bfloat162 h = __float22bfloat162_rn(make_float2(f0, f1));
    float2 hf = __bfloat1622float2(h);
    __nv_bfloat162 l = __float22bfloat162_rn(make_float2(f0 - hf.x, f1 - hf.y));
    hi = *reinterpret_cast<uint32_t*>(&h);
    lo = *reinterpret_cast<uint32_t*>(&l);
}

// ---------------------------------------------------------------------------
// Shared device bodies
// ---------------------------------------------------------------------------
__device__ __forceinline__ void ln_row_split(
    const float* __restrict__ in, const float* __restrict__ g,
    const float* __restrict__ beta,
    __nv_bfloat16* __restrict__ oh, __nv_bfloat16* __restrict__ ol,
    int row, int tid, float* sred)
{
    const float* x = in + (size_t)row * E;
    float v[4];
    float s = 0.f;
#pragma unroll
    for (int i = 0; i < 4; i++) { v[i] = x[tid + i * 256]; s += v[i]; }

    sred[tid] = s; __syncthreads();
#pragma unroll
    for (int off = 128; off > 0; off >>= 1) {
        if (tid < off) sred[tid] += sred[tid + off];
        __syncthreads();
    }
    const float mu = sred[0] * (1.f / E);
    __syncthreads();

    float sq = 0.f;
#pragma unroll
    for (int i = 0; i < 4; i++) { float d = v[i] - mu; sq += d * d; }
    sred[tid] = sq; __syncthreads();
#pragma unroll
    for (int off = 128; off > 0; off >>= 1) {
        if (tid < off) sred[tid] += sred[tid + off];
        __syncthreads();
    }
    const float rstd = rsqrtf(sred[0] * (1.f / E) + 1e-5f);

#pragma unroll
    for (int i = 0; i < 4; i++) {
        int c = tid + i * 256;
        float y = (v[i] - mu) * rstd * g[c] + beta[c];
        __nv_bfloat16 hb = __float2bfloat16(y);
        oh[(size_t)row * E + c] = hb;
        ol[(size_t)row * E + c] = __float2bfloat16(y - __bfloat162float(hb));
    }
}

__device__ __forceinline__ void split_chunk(
    const float* __restrict__ in,
    __nv_bfloat16* __restrict__ hi, __nv_bfloat16* __restrict__ lo,
    int chunk, int tid)
{
    const int i = chunk * 256 + tid;   // float4 index
    float4 v = reinterpret_cast<const float4*>(in)[i];
    uint32_t h0, l0, h1, l1;
    split2(v.x, v.y, h0, l0);
    split2(v.z, v.w, h1, l1);
    reinterpret_cast<uint2*>(hi)[i] = make_uint2(h0, h1);
    reinterpret_cast<uint2*>(lo)[i] = make_uint2(l0, l1);
}

// ---------------------------------------------------------------------------
// prep1: fused LN1 + w_qkv split + build_idx (with inline mask-dtype detect)
// grid = M (LN rows) + 3E*E/1024 (w_qkv chunks) + NBR (block-rows)
// ---------------------------------------------------------------------------
constexpr int QKV_CHUNKS = 3 * E * E / 1024;   // 3072
constexpr int PREP1_GRID = M + QKV_CHUNKS + NBR;

__global__ __launch_bounds__(256) void prep1_kernel(
    const float* __restrict__ x, const float* __restrict__ g1,
    const float* __restrict__ beta1,
    __nv_bfloat16* __restrict__ a1h, __nv_bfloat16* __restrict__ a1l,
    const float* __restrict__ w_qkv,
    __nv_bfloat16* __restrict__ w1h, __nv_bfloat16* __restrict__ w1l,
    const unsigned char* __restrict__ mraw,
    int* __restrict__ idx, unsigned char* __restrict__ bits,
    int* __restrict__ nact)
{
    __shared__ float sred[256];
    __shared__ unsigned char tb[S];
    __shared__ int cnt[256];
    __shared__ int s_is1, s_is2;

    const int t = threadIdx.x;
    const int bid = blockIdx.x;

    if (bid < M) {
        ln_row_split(x, g1, beta1, a1h, a1l, bid, t, sred);
        return;
    }
    if (bid < M + QKV_CHUNKS) {
        split_chunk(w_qkv, w1h, w1l, bid - M, t);
        return;
    }

    // ---- build_idx for block-row br, with inline dtype detect ----
    const int br = bid - M - QKV_CHUNKS;
    if (t == 0) { s_is1 = 0; s_is2 = 0; }
    __syncthreads();
    // detect over first 8KB of raw mask (parallel: 32 bytes per thread)
    {
        int found1 = 0, found2 = 0;
        for (int p = t * 32; p < t * 32 + 32; p++) {
            unsigned char v = mraw[p];
            if (v == 1u    && (p & 3) != 0) found1 = 1;
            if (v == 0x3Fu && (p & 3) == 1) found2 = 1;
        }
        if (found1) s_is1 = 1;
        if (found2) s_is2 = 1;
    }
    __syncthreads();
    const int sz = s_is1 ? 1 : (s_is2 ? 2 : 4);

    int local = 0;
#pragma unroll
    for (int j = 0; j < 8; j++) {
        int c = t * 8 + j;
        unsigned char bt = 0;
        for (int r = 0; r < 8; r++) {
            size_t e = (size_t)(br * 8 + r) * S + c;
            bool nz;
            if (sz == 1)      nz = mraw[e] != 0;
            else if (sz == 2) nz = *reinterpret_cast<const unsigned short*>(mraw + e * 2) != 0;
            else              nz = *reinterpret_cast<const unsigned int*>(mraw + e * 4) != 0;
            bt |= (nz ? 1u : 0u) << r;
        }
        tb[c] = bt;
        local += (bt != 0);
    }
    cnt[t] = local;
    __syncthreads();

    if (t == 0) {
        int run = 0;
        for (int i = 0; i < 256; i++) { int v = cnt[i]; cnt[i] = run; run += v; }
        nact[br] = run < CAP ? run : CAP;
    }
    __syncthreads();

    int pos = cnt[t];
#pragma unroll
    for (int j = 0; j < 8; j++) {
        int c = t * 8 + j;
        if (tb[c] && pos < CAP) {
            idx [br * CAP + pos] = c;
            bits[br * CAP + pos] = tb[c];
            pos++;
        }
    }
}

// ---------------------------------------------------------------------------
// wsplit_rest: w_out + w1 + w2 splits in one launch
// ---------------------------------------------------------------------------
constexpr int WO_CHUNKS = E * E / 1024;     // 1024
constexpr int W1_CHUNKS = MLP * E / 1024;   // 4096
constexpr int W2_CHUNKS = E * MLP / 1024;   // 4096
constexpr int WSPLIT_GRID = WO_CHUNKS + W1_CHUNKS + W2_CHUNKS;

__global__ __launch_bounds__(256) void wsplit_rest_kernel(
    const float* __restrict__ w_out, __nv_bfloat16* __restrict__ w2h, __nv_bfloat16* __restrict__ w2l,
    const float* __restrict__ w1,    __nv_bfloat16* __restrict__ w3h, __nv_bfloat16* __restrict__ w3l,
    const float* __restrict__ w2,    __nv_bfloat16* __restrict__ w4h, __nv_bfloat16* __restrict__ w4l)
{
    const int bid = blockIdx.x;
    const int t = threadIdx.x;
    if (bid < WO_CHUNKS)                 split_chunk(w_out, w2h, w2l, bid, t);
    else if (bid < WO_CHUNKS + W1_CHUNKS) split_chunk(w1, w3h, w3l, bid - WO_CHUNKS, t);
    else                                  split_chunk(w2, w4h, w4l, bid - WO_CHUNKS - W1_CHUNKS, t);
}

// ---------------------------------------------------------------------------
// LayerNorm -> split (standalone, for LN2)
// ---------------------------------------------------------------------------
__global__ __launch_bounds__(256) void ln_split_kernel(
    const float* __restrict__ in, const float* __restrict__ g,
    const float* __restrict__ beta,
    __nv_bfloat16* __restrict__ oh, __nv_bfloat16* __restrict__ ol)
{
    __shared__ float sred[256];
    ln_row_split(in, g, beta, oh, ol, blockIdx.x, threadIdx.x, sred);
}

// ---------------------------------------------------------------------------
// bf16 split-3 GEMM, cp.async + ldmatrix, 2 CTAs/SM. RACE-FIXED pipeline:
// wait -> sync -> compute -> sync -> issue-next-load.
// Block 128x128x32, 256 threads (8 warps, 4m x 2n), warp tile 32x64, 3 stages.
// EPI: 0 = fp32, 1 = fp32 + residual, 2 = bf16 hi/lo split
// ---------------------------------------------------------------------------
constexpr int STAGES = 3;
constexpr int STAGE_BYTES = 32768;
constexpr int GEMM_SMEM = STAGES * STAGE_BYTES;   // 96KB

template <int EPI>
__global__ __launch_bounds__(256, 2) void gemm3(
    const __nv_bfloat16* __restrict__ Ah, const __nv_bfloat16* __restrict__ Al,
    const __nv_bfloat16* __restrict__ Bh, const __nv_bfloat16* __restrict__ Bl,
    const float* __restrict__ bias, const float* __restrict__ R,
    float* __restrict__ C, __nv_bfloat16* __restrict__ Ch, __nv_bfloat16* __restrict__ Cl,
    int Nn, int Kk)
{
    extern __shared__ char smem[];
    const uint32_t sb = smem_u32(smem);

    const int tid  = threadIdx.x;
    const int lane = tid & 31;
    const int wid  = tid >> 5;
    const int wm   = wid >> 1;   // 0..3
    const int wn   = wid & 1;    // 0..1
    const int m0 = blockIdx.y * 128;
    const int n0 = blockIdx.x * 128;

    const int lr  = tid >> 1;
    const int lcb = (tid & 1) * 2;
    const uint32_t sp0 = (uint32_t)(lr * 4 + ((lcb + 0) ^ ((lr >> 1) & 3))) * 16;
    const uint32_t sp1 = (uint32_t)(lr * 4 + ((lcb + 1) ^ ((lr >> 1) & 3))) * 16;
    const __nv_bfloat16* gAh = Ah + (size_t)(m0 + lr) * Kk + lcb * 8;
    const __nv_bfloat16* gAl = Al + (size_t)(m0 + lr) * Kk + lcb * 8;
    const __nv_bfloat16* gBh = Bh + (size_t)(n0 + lr) * Kk + lcb * 8;
    const __nv_bfloat16* gBl = Bl + (size_t)(n0 + lr) * Kk + lcb * 8;

    auto load_stage = [&](int stage, int kt) {
        const uint32_t s0 = sb + stage * STAGE_BYTES;
        const int go = kt * 32;
        cp_async16(s0 + sp0,         gAh + go);
        cp_async16(s0 + sp1,         gAh + go + 8);
        cp_async16(s0 + sp0 + 8192,  gAl + go);
        cp_async16(s0 + sp1 + 8192,  gAl + go + 8);
        cp_async16(s0 + sp0 + 16384, gBh + go);
        cp_async16(s0 + sp1 + 16384, gBh + go + 8);
        cp_async16(s0 + sp0 + 24576, gBl + go);
        cp_async16(s0 + sp1 + 24576, gBl + go + 8);
    };

    const int arow0 = wm * 32 + (lane & 15);
    const int achb  = lane >> 4;
    const int brow0 = wn * 64 + (lane & 7) + ((lane >> 4) << 3);
    const int bchb  = (lane >> 3) & 1;

    float acc[2][8][4];
#pragma unroll
    for (int mi = 0; mi < 2; mi++)
#pragma unroll
        for (int ni = 0; ni < 8; ni++)
#pragma unroll
            for (int q = 0; q < 4; q++) acc[mi][ni][q] = 0.f;

    const int T = Kk >> 5;

    load_stage(0, 0); CP_COMMIT();
    load_stage(1, 1); CP_COMMIT();

    int stage = 0;
    for (int t = 0; t < T; t++) {
        CP_WAIT(1);
        __syncthreads();

        const uint32_t base = sb + stage * STAGE_BYTES;
#pragma unroll
        for (int ks = 0; ks < 2; ks++) {
            uint4 ah[2], al[2];
#pragma unroll
            for (int mi = 0; mi < 2; mi++) {
                int row = arow0 + mi * 16;
                int c = ks * 2 + achb;
                uint32_t ad = base + (uint32_t)(row * 4 + (c ^ ((row >> 1) & 3))) * 16;
                ah[mi] = ldmx4(ad);
                al[mi] = ldmx4(ad + 8192);
            }
            uint4 bh[4], bl[4];
#pragma unroll
            for (int np = 0; np < 4; np++) {
                int row = brow0 + np * 16;
                int c = ks * 2 + bchb;
                uint32_t bd = base + 16384 + (uint32_t)(row * 4 + (c ^ ((row >> 1) & 3))) * 16;
                bh[np] = ldmx4(bd);
                bl[np] = ldmx4(bd + 8192);
            }
            uint32_t bh0[8], bh1[8], bl0[8], bl1[8];
#pragma unroll
            for (int np = 0; np < 4; np++) {
                bh0[2 * np] = bh[np].x; bh0[2 * np + 1] = bh[np].z;
                bh1[2 * np] = bh[np].y; bh1[2 * np + 1] = bh[np].w;
                bl0[2 * np] = bl[np].x; bl0[2 * np + 1] = bl[np].z;
                bl1[2 * np] = bl[np].y; bl1[2 * np + 1] = bl[np].w;
            }
#pragma unroll
            for (int mi = 0; mi < 2; mi++)
#pragma unroll
                for (int ni = 0; ni < 8; ni++)
                    mma_bf16(acc[mi][ni], ah[mi], bh0[ni], bh1[ni]);
#pragma unroll
            for (int mi = 0; mi < 2; mi++)
#pragma unroll
                for (int ni = 0; ni < 8; ni++)
                    mma_bf16(acc[mi][ni], ah[mi], bl0[ni], bl1[ni]);
#pragma unroll
            for (int mi = 0; mi < 2; mi++)
#pragma unroll
                for (int ni = 0; ni < 8; ni++)
                    mma_bf16(acc[mi][ni], al[mi], bh0[ni], bh1[ni]);
        }
        __syncthreads();   // all reads of this stage done before refill
        if (t + 2 < T) { load_stage((stage + 2) % STAGES, t + 2); CP_COMMIT(); }
        stage = (stage + 1) % STAGES;
    }

    // ---- epilogue ----
    const int rb = m0 + wm * 32 + (lane >> 2);
    const int cb = n0 + wn * 64 + (lane & 3) * 2;
#pragma unroll
    for (int mi = 0; mi < 2; mi++) {
#pragma unroll
        for (int ni = 0; ni < 8; ni++) {
            const int col = cb + ni * 8;
            const float2 bv = *reinterpret_cast<const float2*>(&bias[col]);
#pragma unroll
            for (int half = 0; half < 2; half++) {
                const size_t row = (size_t)(rb + mi * 16 + half * 8);
                float ox = acc[mi][ni][half * 2 + 0] + bv.x;
                float oy = acc[mi][ni][half * 2 + 1] + bv.y;
                if (EPI == 1) {
                    float2 rv = *reinterpret_cast<const float2*>(&R[row * Nn + col]);
                    ox += rv.x; oy += rv.y;
                }
                if (EPI == 2) {
                    uint32_t hh, ll;
                    split2(ox, oy, hh, ll);
                    *reinterpret_cast<uint32_t*>(&Ch[row * Nn + col]) = hh;
                    *reinterpret_cast<uint32_t*>(&Cl[row * Nn + col]) = ll;
                } else {
                    *reinterpret_cast<float2*>(&C[row * Nn + col]) = make_float2(ox, oy);
                }
            }
        }
    }
}

// ---------------------------------------------------------------------------
// Block-sparse attention (unchanged structure -> clean profile this round)
// ---------------------------------------------------------------------------
__global__ __launch_bounds__(256) void attn_sparse_kernel(
    const float* __restrict__ qkv,
    const int* __restrict__ idx_g, const unsigned char* __restrict__ bits_g,
    const int* __restrict__ nact_g,
    __nv_bfloat16* __restrict__ cxh, __nv_bfloat16* __restrict__ cxl)
{
    __shared__ float Qs[8][64];
    __shared__ float Ss[8][CAP];
    __shared__ int sidx[CAP];
    __shared__ unsigned char sbits[CAP];

    const int tid = threadIdx.x;
    const int br = blockIdx.x;
    const int hd = blockIdx.y;
    const int b  = blockIdx.z;
    const int q0 = br * 8;
    const int n  = nact_g[br];

    for (int i = tid; i < CAP; i += 256) {
        sidx[i]  = idx_g[br * CAP + i];
        sbits[i] = bits_g[br * CAP + i];
    }

    const size_t base = (size_t)b * S * (3 * E);
    const float* Qbase = qkv + base + (size_t)q0 * (3 * E) + hd * DH;
    const float* Kbase = qkv + base + E + hd * DH;
    const float* Vbase = qkv + base + 2 * E + hd * DH;

    {
        int r = tid >> 5;
        int c = (tid & 31) * 2;
        *reinterpret_cast<float2*>(&Qs[r][c]) =
            *reinterpret_cast<const float2*>(Qbase + (size_t)r * (3 * E) + c);
    }
    __syncthreads();

    for (int s = tid; s < n; s += 256) {
        const float4* kr = reinterpret_cast<const float4*>(Kbase + (size_t)sidx[s] * (3 * E));
        float a[8];
#pragma unroll
        for (int r = 0; r < 8; r++) a[r] = 0.f;
#pragma unroll 4
        for (int d4 = 0; d4 < 16; d4++) {
            float4 kv = kr[d4];
#pragma unroll
            for (int r = 0; r < 8; r++) {
                float4 qv = reinterpret_cast<const float4*>(&Qs[r][0])[d4];
                a[r] = fmaf(kv.x, qv.x, a[r]);
                a[r] = fmaf(kv.y, qv.y, a[r]);
                a[r] = fmaf(kv.z, qv.z, a[r]);
                a[r] = fmaf(kv.w, qv.w, a[r]);
            }
        }
        unsigned bt = sbits[s];
#pragma unroll
        for (int r = 0; r < 8; r++)
            Ss[r][s] = ((bt >> r) & 1) ? a[r] * SCALE : -1e9f;
    }
    __syncthreads();

    const int w = tid >> 5, l = tid & 31;
    float mx = -3.0e38f;
    for (int s = l; s < n; s += 32) mx = fmaxf(mx, Ss[w][s]);
#pragma unroll
    for (int o = 16; o; o >>= 1) mx = fmaxf(mx, __shfl_xor_sync(0xFFFFFFFFu, mx, o));
    float sm = 0.f;
    for (int s = l; s < n; s += 32) {
        float p = __expf(Ss[w][s] - mx);
        Ss[w][s] = p;
        sm += p;
    }
#pragma unroll
    for (int o = 16; o; o >>= 1) sm += __shfl_xor_sync(0xFFFFFFFFu, sm, o);
    const float inv = 1.f / sm;
    __syncwarp();

    float ax = 0.f, ay = 0.f;
    int s = 0;
    for (; s + 4 <= n; s += 4) {
#pragma unroll
        for (int u = 0; u < 4; u++) {
            float p = Ss[w][s + u];
            const float2 v = *reinterpret_cast<const float2*>(
                Vbase + (size_t)sidx[s + u] * (3 * E) + 2 * l);
            ax = fmaf(p, v.x, ax);
            ay = fmaf(p, v.y, ay);
        }
    }
    for (; s < n; s++) {
        float p = Ss[w][s];
        const float2 v = *reinterpret_cast<const float2*>(
            Vbase + (size_t)sidx[s] * (3 * E) + 2 * l);
        ax = fmaf(p, v.x, ax);
        ay = fmaf(p, v.y, ay);
    }
    float ox = ax * inv, oy = ay * inv;
    uint32_t hh, ll;
    split2(ox, oy, hh, ll);
    const size_t off = ((size_t)b * S + q0 + w) * E + hd * DH + 2 * l;
    *reinterpret_cast<uint32_t*>(&cxh[off]) = hh;
    *reinterpret_cast<uint32_t*>(&cxl[off]) = ll;
}

// ---------------------------------------------------------------------------
// Launch: 8 launches; attention is the 4th (profiled slot)
// ---------------------------------------------------------------------------
extern "C" void kernel_launch(void* const* d_in, const int* in_sizes, int n_in,
                              void* d_out, int out_size)
{
    const float*         x      = (const float*)d_in[0];
    const unsigned char* mraw   = (const unsigned char*)d_in[1];
    const float*         w_qkv  = (const float*)d_in[2];
    const float*         b_qkv  = (const float*)d_in[3];
    const float*         w_out  = (const float*)d_in[4];
    const float*         b_out  = (const float*)d_in[5];
    const float*         g1     = (const float*)d_in[6];
    const float*         beta1  = (const float*)d_in[7];
    const float*         g2     = (const float*)d_in[8];
    const float*         beta2  = (const float*)d_in[9];
    const float*         w1     = (const float*)d_in[10];
    const float*         bias1  = (const float*)d_in[11];
    const float*         w2     = (const float*)d_in[12];
    const float*         bias2  = (const float*)d_in[13];
    float*               out    = (float*)d_out;

    __nv_bfloat16 *a1h, *a1l, *w1h, *w1l, *w2h, *w2l, *w3h, *w3l, *w4h, *w4l;
    __nv_bfloat16 *cxh, *cxl, *a2h, *a2l, *m1h, *m1l;
    float *qkv, *att;
    unsigned char *bits;
    int *idx, *nact;
    cudaGetSymbolAddress((void**)&a1h, g_a1h); cudaGetSymbolAddress((void**)&a1l, g_a1l);
    cudaGetSymbolAddress((void**)&w1h, g_w1h); cudaGetSymbolAddress((void**)&w1l, g_w1l);
    cudaGetSymbolAddress((void**)&w2h, g_w2h); cudaGetSymbolAddress((void**)&w2l, g_w2l);
    cudaGetSymbolAddress((void**)&w3h, g_w3h); cudaGetSymbolAddress((void**)&w3l, g_w3l);
    cudaGetSymbolAddress((void**)&w4h, g_w4h); cudaGetSymbolAddress((void**)&w4l, g_w4l);
    cudaGetSymbolAddress((void**)&cxh, g_cxh); cudaGetSymbolAddress((void**)&cxl, g_cxl);
    cudaGetSymbolAddress((void**)&a2h, g_a2h); cudaGetSymbolAddress((void**)&a2l, g_a2l);
    cudaGetSymbolAddress((void**)&m1h, g_m1h); cudaGetSymbolAddress((void**)&m1l, g_m1l);
    cudaGetSymbolAddress((void**)&qkv, g_qkv);
    cudaGetSymbolAddress((void**)&att, g_att);
    cudaGetSymbolAddress((void**)&idx, g_idx);
    cudaGetSymbolAddress((void**)&bits, g_bits);
    cudaGetSymbolAddress((void**)&nact, g_nact);

    cudaFuncSetAttribute(gemm3<0>, cudaFuncAttributeMaxDynamicSharedMemorySize, GEMM_SMEM);
    cudaFuncSetAttribute(gemm3<1>, cudaFuncAttributeMaxDynamicSharedMemorySize, GEMM_SMEM);
    cudaFuncSetAttribute(gemm3<2>, cudaFuncAttributeMaxDynamicSharedMemorySize, GEMM_SMEM);

    // 1. prep1: LN1 + w_qkv split + mask index build
    prep1_kernel<<<PREP1_GRID, 256>>>(x, g1, beta1, a1h, a1l,
                                      w_qkv, w1h, w1l, mraw, idx, bits, nact);
    // 2. QKV projection
    gemm3<0><<<dim3(3 * E / 128, M / 128), 256, GEMM_SMEM>>>(
        a1h, a1l, w1h, w1l, b_qkv, nullptr, qkv, nullptr, nullptr, 3 * E, E);
    // 3. remaining weight splits
    wsplit_rest_kernel<<<WSPLIT_GRID, 256>>>(w_out, w2h, w2l, w1, w3h, w3l, w2, w4h, w4l);
    // 4. block-sparse attention  <-- profiled launch
    attn_sparse_kernel<<<dim3(NBR, H, B), 256>>>(qkv, idx, bits, nact, cxh, cxl);
    // 5. out projection + residual x
    gemm3<1><<<dim3(E / 128, M / 128), 256, GEMM_SMEM>>>(
        cxh, cxl, w2h, w2l, b_out, x, att, nullptr, nullptr, E, E);
    // 6. LN2
    ln_split_kernel<<<M, 256>>>(att, g2, beta2, a2h, a2l);
    // 7. MLP linear1 (split out)
    gemm3<2><<<dim3(MLP / 128, M / 128), 256, GEMM_SMEM>>>(
        a2h, a2l, w3h, w3l, bias1, nullptr, nullptr, m1h, m1l, MLP, E);
    // 8. MLP linear2 + residual x -> output
    gemm3<1><<<dim3(E / 128, M / 128), 256, GEMM_SMEM>>>(
        m1h, m1l, w4h, w4l, bias2, x, out, nullptr, nullptr, E, MLP);
}